// round 9
// baseline (speedup 1.0000x reference)
#include <cuda_runtime.h>
#include <math.h>

// Problem constants
#define CC      50
#define HID     64
#define NB      10
#define NPATHS  5
#define NLAYERS 6
#define BB      64
#define LL      514
#define TT      512
#define NT      (BB*TT)
#define MAXR    0.06f
#define HALFBAR 0.05f
#define PI_F    3.14159265358979f

// wi(r) interpolation table
#define TKNOTS  256
#define TROWS   260           // rows: knot -1 .. 258 (clamped duplicates)

// Kernel config: 4 warps/block, 4 triplets per warp
#define TRIPW    4
#define WPB      4
#define NTHREADS 128
#define TPB      (WPB*TRIPW)      // 16
#define NBLOCKS  (NT/TPB)         // 2048

#define HVT_TRIP   624            // 12 rows * 52 (3 H + 9 VT), 52-stride for bank spread

__device__ float g_s1[NLAYERS][CC];
__device__ float g_wbar[NLAYERS][NPATHS*CC];
// wi table: [layer][row][lane-packed 100]: for lane k, 4 floats =
// (path0 c=2k, path0 c=2k+1, path1 c=2k, path1 c=2k+1), fcut folded in.
__device__ float g_witab[NLAYERS][TROWS][100];

__device__ __forceinline__ float siluf(float x){ return x/(1.f+__expf(-x)); }
__device__ __forceinline__ float sigmf(float x){ return 1.f/(1.f+__expf(-x)); }

// ---------------------------------------------------------------------------
// Serial part only: node-1 scalar trajectory (6 chained 50x50 matvecs)
// ---------------------------------------------------------------------------
__global__ void e3nn_s1(const float* __restrict__ W_embed,
                        const float* __restrict__ Ws)
{
    __shared__ float s1[CC];
    const int tid = threadIdx.x;
    if (tid < CC) s1[tid] = W_embed[tid] + W_embed[CC + tid];
    __syncthreads();
    for (int l = 0; l < NLAYERS; l++) {
        float acc = 0.f;
        if (tid < CC) {
            g_s1[l][tid] = s1[tid];
            #pragma unroll 5
            for (int c = 0; c < CC; c++) acc += s1[c]*Ws[(l*CC + c)*CC + tid];
        }
        __syncthreads();
        if (tid < CC) s1[tid] = siluf(acc);
        __syncthreads();
    }
}

// ---------------------------------------------------------------------------
// Parallel table build: wi(r) knots for the inter edge (attr [1,0]) AND the
// constant intra-edge weights g_wbar (attr [0,1], r=HALF_BAR).
// grid = NLAYERS*(TROWS+1) blocks of 128 threads.
// ---------------------------------------------------------------------------
__global__ void e3nn_build_table(const float* __restrict__ Wr1,
                                 const float* __restrict__ br1,
                                 const float* __restrict__ Wr2)
{
    const int l   = blockIdx.x / (TROWS+1);
    const int row = blockIdx.x - l*(TROWS+1);
    const bool intra = (row == TROWS);
    float r;
    if (intra) r = HALFBAR;
    else {
        int knot = row - 1;
        knot = knot < 0 ? 0 : (knot > TKNOTS ? TKNOTS : knot);
        r = (float)knot * (MAXR/(float)TKNOTS);
    }
    __shared__ float emb[NB+2], hid[HID], fcs;
    const int tid = threadIdx.x;
    if (tid == 0) {
        float tt = fminf(fmaxf(r/MAXR, 0.f), 1.f);
        float fc = 0.5f*(cosf(PI_F*tt) + 1.f);
        fcs = fc;
        const float width = MAXR/(float)(NB-1);
        for (int i = 0; i < NB; i++) {
            float ci = MAXR*(float)i/(float)(NB-1);
            float d  = (r - ci)/width;
            emb[i]   = __expf(-d*d)*fc;
        }
        emb[NB]   = intra ? 0.f : 1.f;
        emb[NB+1] = intra ? 1.f : 0.f;
    }
    __syncthreads();
    if (tid < HID) {
        float acc = br1[l*HID + tid];
        #pragma unroll
        for (int i = 0; i < NB+2; i++) acc += emb[i]*Wr1[(l*(NB+2)+i)*HID + tid];
        hid[tid] = siluf(acc);
    }
    __syncthreads();
    if (intra) {
        for (int ch = tid; ch < NPATHS*CC; ch += 128) {
            float acc = 0.f;
            for (int j = 0; j < HID; j++)
                acc += hid[j]*Wr2[(l*HID + j)*(NPATHS*CC) + ch];
            g_wbar[l][ch] = acc*fcs;
        }
    } else if (tid < 100) {
        int k = tid >> 2, sub = tid & 3;
        int ch = (sub < 2) ? (2*k + sub) : (50 + 2*k + (sub-2));
        float acc = 0.f;
        for (int j = 0; j < HID; j++)
            acc += hid[j]*Wr2[(l*HID + j)*(NPATHS*CC) + ch];
        g_witab[l][row][tid] = acc*fcs;
    }
}

// ---------------------------------------------------------------------------
// Main fused kernel: barrier-free layer loop; weights streamed via __ldg (L1),
// hb scratch is warp-private shared memory.
// ---------------------------------------------------------------------------
__global__ void __launch_bounds__(NTHREADS, 3) e3nn_main(
    const float* __restrict__ y,
    const float* __restrict__ W_embed,
    const float* __restrict__ Ws,
    const float* __restrict__ Wv,
    const float* __restrict__ Wg,
    const float* __restrict__ W_out,
    float* __restrict__ outp)
{
    __shared__ float sm[TPB*HVT_TRIP];
    const int tid  = threadIdx.x;
    const int w    = tid >> 5;
    const int lane = tid & 31;
    const int k    = lane;
    const bool act = (k < 25);
    const int c0   = 2*k;
    const int c1   = c0 + 1;

    const int gbase = blockIdx.x*TPB + w*TRIPW;
    float* hbW = sm + (w*TRIPW)*HVT_TRIP;

    // ---- geometry init: lanes 0..3 handle one triplet each ----
    float myUIx=0.f, myUIy=0.f, myU3x=0.f, myU3y=0.f, myR=1e9f;
    if (lane < TRIPW) {
        int g = gbase + lane;
        int b = g >> 9;
        int t = g & 511;
        const float* yb = y + ((size_t)b*LL + t)*6;
        float p0x = yb[0],  p0y = yb[1];
        float p1x = yb[6],  p1y = yb[7];
        float a   = yb[8];
        float ex = p0x - p1x, ey = p0y - p1y;
        float r  = sqrtf(ex*ex + ey*ey);
        float inv = 1.f/(r + 1e-12f);
        myUIx = ex*inv; myUIy = ey*inv;
        myU3x = sinf(a); myU3y = -cosf(a);
        myR = r;
    }
    float uIx[TRIPW], uIy[TRIPW], u3x[TRIPW], u3y[TRIPW], rT[TRIPW];
    #pragma unroll
    for (int t = 0; t < TRIPW; t++) {
        uIx[t] = __shfl_sync(0xffffffffu, myUIx, t);
        uIy[t] = __shfl_sync(0xffffffffu, myUIy, t);
        u3x[t] = __shfl_sync(0xffffffffu, myU3x, t);
        u3y[t] = __shfl_sync(0xffffffffu, myU3y, t);
        rT[t]  = __shfl_sync(0xffffffffu, myR,  t);
    }

    // ---- register state ----
    float s[TRIPW][3][2];
    float v[TRIPW][3][2][3];
    #pragma unroll
    for (int t = 0; t < TRIPW; t++)
        #pragma unroll
        for (int n = 0; n < 3; n++)
            #pragma unroll
            for (int q = 0; q < 2; q++) {
                s[t][n][q] = 0.f;
                v[t][n][q][0] = v[t][n][q][1] = v[t][n][q][2] = 0.f;
            }
    if (act) {
        float e00 = W_embed[c0],      e01 = W_embed[c1];
        float e10 = W_embed[CC+c0],   e11 = W_embed[CC+c1];
        float e20 = W_embed[2*CC+c0], e21 = W_embed[2*CC+c1];
        #pragma unroll
        for (int t = 0; t < TRIPW; t++) {
            s[t][0][0] = e00 + e20;  s[t][0][1] = e01 + e21;
            s[t][1][0] = e00 + e10;  s[t][1][1] = e01 + e11;
            s[t][2][0] = e00 + e20;  s[t][2][1] = e01 + e21;
        }
    }

    for (int l = 0; l < NLAYERS; l++) {
        // ---- inter-edge weights via Catmull-Rom table lookup ----
        float wi[TRIPW][4];
        if (act) {
            #pragma unroll
            for (int t = 0; t < TRIPW; t++) {
                float xr = rT[t]*((float)TKNOTS/MAXR);
                float valid = (xr < (float)TKNOTS) ? 1.f : 0.f;
                xr = fminf(xr, (float)TKNOTS - 0.001f);
                float jf = floorf(xr);
                int j = (int)jf;
                float u = xr - jf;
                float u2 = u*u, u3 = u2*u;
                float cw0 = 0.5f*(-u + 2.f*u2 - u3);
                float cw1 = 0.5f*(2.f - 5.f*u2 + 3.f*u3);
                float cw2 = 0.5f*(u + 4.f*u2 - 3.f*u3);
                float cw3 = 0.5f*(-u2 + u3);
                const float* tb = &g_witab[l][j][4*k];
                float4 r0 = *(const float4*)(tb);
                float4 r1 = *(const float4*)(tb + 100);
                float4 r2 = *(const float4*)(tb + 200);
                float4 r3 = *(const float4*)(tb + 300);
                wi[t][0] = valid*(cw0*r0.x + cw1*r1.x + cw2*r2.x + cw3*r3.x);
                wi[t][1] = valid*(cw0*r0.y + cw1*r1.y + cw2*r2.y + cw3*r3.y);
                wi[t][2] = valid*(cw0*r0.z + cw1*r1.z + cw2*r2.z + cw3*r3.z);
                wi[t][3] = valid*(cw0*r0.w + cw1*r1.w + cw2*r2.w + cw3*r3.w);
            }
        }
        // ---- messages -> hb (warp-private region) ----
        if (act) {
            float wb0[2], wb1[2], wb2[2], wb3[2], wb4[2], s1v[2];
            #pragma unroll
            for (int q = 0; q < 2; q++) {
                int cq = c0 + q;
                wb0[q] = g_wbar[l][cq];
                wb1[q] = g_wbar[l][50+cq];
                wb2[q] = g_wbar[l][100+cq];
                wb3[q] = g_wbar[l][150+cq];
                wb4[q] = g_wbar[l][200+cq];
                s1v[q] = g_s1[l][cq];
            }
            #pragma unroll
            for (int t = 0; t < TRIPW; t++) {
                float* hb = hbW + t*HVT_TRIP;
                float H3[2], H4[2], H5[2];
                float V3[2][3], V4[2][3], V5[2][3];
                float ux = u3x[t], uy = u3y[t];
                #pragma unroll
                for (int q = 0; q < 2; q++) {
                    float s4  = s[t][1][q];
                    float v4x = v[t][1][q][0], v4y = v[t][1][q][1], v4z = v[t][1][q][2];
                    H4[q] = s4 + wi[t][q]*s1v[q];
                    float w1i = wi[t][2+q]*s1v[q];
                    V4[q][0] = v4x + w1i*uIx[t];
                    V4[q][1] = v4y + w1i*uIy[t];
                    V4[q][2] = v4z;
                    float dotc = v4x*ux + v4y*uy;
                    float base = wb0[q]*s4;
                    H3[q] = s[t][0][q] + base + wb2[q]*dotc;
                    H5[q] = s[t][2][q] + base - wb2[q]*dotc;
                    float cx = -v4z*uy, cy = v4z*ux, cz = v4x*uy - v4y*ux;
                    float y2x = dotc*ux - v4x*(1.f/3.f);
                    float y2y = dotc*uy - v4y*(1.f/3.f);
                    float y2z = -v4z*(1.f/3.f);
                    float sx = wb1[q]*s4;
                    V3[q][0] = v[t][0][q][0] + sx*ux + wb3[q]*cx + wb4[q]*y2x;
                    V3[q][1] = v[t][0][q][1] + sx*uy + wb3[q]*cy + wb4[q]*y2y;
                    V3[q][2] = v[t][0][q][2]         + wb3[q]*cz + wb4[q]*y2z;
                    V5[q][0] = v[t][2][q][0] - sx*ux - wb3[q]*cx + wb4[q]*y2x;
                    V5[q][1] = v[t][2][q][1] - sx*uy - wb3[q]*cy + wb4[q]*y2y;
                    V5[q][2] = v[t][2][q][2]         - wb3[q]*cz + wb4[q]*y2z;
                }
                *(float2*)&hb[0*52 + c0] = make_float2(H3[0], H3[1]);
                *(float2*)&hb[1*52 + c0] = make_float2(H4[0], H4[1]);
                *(float2*)&hb[2*52 + c0] = make_float2(H5[0], H5[1]);
                #pragma unroll
                for (int d = 0; d < 3; d++) {
                    *(float2*)&hb[156 + (0*3+d)*52 + c0] = make_float2(V3[0][d], V3[1][d]);
                    *(float2*)&hb[156 + (1*3+d)*52 + c0] = make_float2(V4[0][d], V4[1][d]);
                    *(float2*)&hb[156 + (2*3+d)*52 + c0] = make_float2(V5[0][d], V5[1][d]);
                }
            }
        }
        __syncwarp();   // order hb writes before reads (warp-local)
        // ---- node update: weights via __ldg (L1-resident, no staging) ----
        if (act) {
            const float* wsb = Ws + l*CC*CC + c0;
            const float* wgb = Wg + l*CC*CC + c0;
            const float* wvb = Wv + l*CC*CC + c0;
            #pragma unroll 1
            for (int n = 0; n < 3; n++) {
                float aS[TRIPW][2], aG[TRIPW][2], aVx[TRIPW][2], aVy[TRIPW][2], aVz[TRIPW][2];
                #pragma unroll
                for (int t = 0; t < TRIPW; t++) {
                    aS[t][0]=aS[t][1]=aG[t][0]=aG[t][1]=0.f;
                    aVx[t][0]=aVx[t][1]=aVy[t][0]=aVy[t][1]=aVz[t][0]=aVz[t][1]=0.f;
                }
                #pragma unroll 1
                for (int cg = 0; cg < 48; cg += 4) {
                    float2 wsv[4], wgv[4], wvv[4];
                    #pragma unroll
                    for (int i = 0; i < 4; i++) {
                        wsv[i] = __ldg((const float2*)(wsb + (cg+i)*CC));
                        wgv[i] = __ldg((const float2*)(wgb + (cg+i)*CC));
                        wvv[i] = __ldg((const float2*)(wvb + (cg+i)*CC));
                    }
                    #pragma unroll
                    for (int t = 0; t < TRIPW; t++) {
                        const float* hb = hbW + t*HVT_TRIP;
                        float4 h4  = *(const float4*)&hb[n*52 + cg];
                        float4 vx4 = *(const float4*)&hb[156 + (n*3+0)*52 + cg];
                        float4 vy4 = *(const float4*)&hb[156 + (n*3+1)*52 + cg];
                        float4 vz4 = *(const float4*)&hb[156 + (n*3+2)*52 + cg];
                        #pragma unroll
                        for (int i = 0; i < 4; i++) {
                            float hc  = (i==0)?h4.x :(i==1)?h4.y :(i==2)?h4.z :h4.w;
                            float vxc = (i==0)?vx4.x:(i==1)?vx4.y:(i==2)?vx4.z:vx4.w;
                            float vyc = (i==0)?vy4.x:(i==1)?vy4.y:(i==2)?vy4.z:vy4.w;
                            float vzc = (i==0)?vz4.x:(i==1)?vz4.y:(i==2)?vz4.z:vz4.w;
                            aS[t][0]  += hc*wsv[i].x;  aS[t][1]  += hc*wsv[i].y;
                            aG[t][0]  += hc*wgv[i].x;  aG[t][1]  += hc*wgv[i].y;
                            aVx[t][0] += vxc*wvv[i].x; aVx[t][1] += vxc*wvv[i].y;
                            aVy[t][0] += vyc*wvv[i].x; aVy[t][1] += vyc*wvv[i].y;
                            aVz[t][0] += vzc*wvv[i].x; aVz[t][1] += vzc*wvv[i].y;
                        }
                    }
                }
                // tail: c = 48, 49
                {
                    float2 wsv[2], wgv[2], wvv[2];
                    #pragma unroll
                    for (int i = 0; i < 2; i++) {
                        wsv[i] = __ldg((const float2*)(wsb + (48+i)*CC));
                        wgv[i] = __ldg((const float2*)(wgb + (48+i)*CC));
                        wvv[i] = __ldg((const float2*)(wvb + (48+i)*CC));
                    }
                    #pragma unroll
                    for (int t = 0; t < TRIPW; t++) {
                        const float* hb = hbW + t*HVT_TRIP;
                        float2 h2  = *(const float2*)&hb[n*52 + 48];
                        float2 vx2 = *(const float2*)&hb[156 + (n*3+0)*52 + 48];
                        float2 vy2 = *(const float2*)&hb[156 + (n*3+1)*52 + 48];
                        float2 vz2 = *(const float2*)&hb[156 + (n*3+2)*52 + 48];
                        #pragma unroll
                        for (int i = 0; i < 2; i++) {
                            float hc  = (i==0)?h2.x :h2.y;
                            float vxc = (i==0)?vx2.x:vx2.y;
                            float vyc = (i==0)?vy2.x:vy2.y;
                            float vzc = (i==0)?vz2.x:vz2.y;
                            aS[t][0]  += hc*wsv[i].x;  aS[t][1]  += hc*wsv[i].y;
                            aG[t][0]  += hc*wgv[i].x;  aG[t][1]  += hc*wgv[i].y;
                            aVx[t][0] += vxc*wvv[i].x; aVx[t][1] += vxc*wvv[i].y;
                            aVy[t][0] += vyc*wvv[i].x; aVy[t][1] += vyc*wvv[i].y;
                            aVz[t][0] += vzc*wvv[i].x; aVz[t][1] += vzc*wvv[i].y;
                        }
                    }
                }
                #pragma unroll
                for (int t = 0; t < TRIPW; t++)
                    #pragma unroll
                    for (int q = 0; q < 2; q++) {
                        float gg = sigmf(aG[t][q]);
                        s[t][n][q]    = siluf(aS[t][q]);
                        v[t][n][q][0] = aVx[t][q]*gg;
                        v[t][n][q][1] = aVy[t][q]*gg;
                        v[t][n][q][2] = aVz[t][q]*gg;
                    }
            }
        }
        __syncwarp();   // GEMM hb reads done before next layer's writes
    }

    // ---- epilogue ----
    float p[TRIPW][9];
    #pragma unroll
    for (int t = 0; t < TRIPW; t++)
        #pragma unroll
        for (int i = 0; i < 9; i++) p[t][i] = 0.f;
    if (act) {
        #pragma unroll
        for (int q = 0; q < 2; q++) {
            float wo = W_out[c0+q];
            #pragma unroll
            for (int t = 0; t < TRIPW; t++)
                #pragma unroll
                for (int n = 0; n < 3; n++)
                    #pragma unroll
                    for (int d = 0; d < 3; d++)
                        p[t][n*3+d] += wo*v[t][n][q][d];
        }
    }
    #pragma unroll
    for (int off = 16; off > 0; off >>= 1)
        #pragma unroll
        for (int t = 0; t < TRIPW; t++)
            #pragma unroll
            for (int i = 0; i < 9; i++)
                p[t][i] += __shfl_xor_sync(0xffffffffu, p[t][i], off);
    if (lane == 0) {
        #pragma unroll
        for (int t = 0; t < TRIPW; t++) {
            int g = gbase + t;
            int b = g >> 9;
            int tt = g & 511;
            float rx = p[t][0] + p[t][3] + p[t][6];
            float ry = p[t][1] + p[t][4] + p[t][7];
            float offx = -HALFBAR*u3x[t], offy = -HALFBAR*u3y[t];
            float rz = (offx*p[t][1] - offy*p[t][0]) - (offx*p[t][7] - offy*p[t][6]);
            float* o = outp + ((size_t)b*LL + (tt+1))*3;
            o[0] = rx; o[1] = ry; o[2] = rz;
        }
    }
}

// ---------------------------------------------------------------------------
extern "C" void kernel_launch(void* const* d_in, const int* in_sizes, int n_in,
                              void* d_out, int out_size)
{
    const float* y       = (const float*)d_in[0];
    const float* W_embed = (const float*)d_in[1];
    const float* Wr1     = (const float*)d_in[2];
    const float* br1     = (const float*)d_in[3];
    const float* Wr2     = (const float*)d_in[4];
    const float* Ws      = (const float*)d_in[5];
    const float* Wv      = (const float*)d_in[6];
    const float* Wg      = (const float*)d_in[7];
    const float* W_out   = (const float*)d_in[8];
    float* outp = (float*)d_out;

    cudaMemsetAsync(d_out, 0, (size_t)out_size*sizeof(float), 0);
    e3nn_s1<<<1, 64>>>(W_embed, Ws);
    e3nn_build_table<<<NLAYERS*(TROWS+1), 128>>>(Wr1, br1, Wr2);
    e3nn_main<<<NBLOCKS, NTHREADS>>>(y, W_embed, Ws, Wv, Wg, W_out, outp);
}

// round 11
// speedup vs baseline: 1.2285x; 1.2285x over previous
#include <cuda_runtime.h>
#include <math.h>

// Problem constants
#define CC      50
#define HID     64
#define NB      10
#define NPATHS  5
#define NLAYERS 6
#define BB      64
#define LL      514
#define TT      512
#define NT      (BB*TT)
#define MAXR    0.06f
#define HALFBAR 0.05f
#define PI_F    3.14159265358979f

// wi(r) interpolation table
#define TKNOTS  256
#define TROWS   260

// Kernel config: 4 warps/block, 4 triplets per warp (2 t-pairs), 3 blocks/SM
#define TRIPW    4
#define WPB      4
#define NTHREADS 128
#define TPB      (WPB*TRIPW)      // 16
#define NBLOCKS  (NT/TPB)         // 2048

// Shared memory layout (float offsets)
// Weights: Wss [0,2600) Wgs [2600,5200) Wvs [5200,7800) (rows 50,51 zeroed)
#define WSS_OFF    0
#define WGS_OFF    2600
#define WVS_OFF    5200
#define OFF_HVT    7800
// hb per warp: 2 t-pairs, each 12 rows * 104 ( [c][t] packed, 52 c incl pads )
#define HB_ROW     104
#define HB_TP      (12*HB_ROW)    // 1248
#define HB_WARP    (2*HB_TP)      // 2496
#define SMEM_FLOATS (OFF_HVT + WPB*HB_WARP)   // 17784
#define SMEM_BYTES  (SMEM_FLOATS*4)           // 71136

typedef unsigned long long u64;

__device__ float g_s1[NLAYERS][CC];
__device__ float g_wbar[NLAYERS][NPATHS*CC];
__device__ float g_witab[NLAYERS][TROWS][100];
__device__ float g_dummy;

__device__ __forceinline__ float siluf(float x){ return x/(1.f+__expf(-x)); }
__device__ __forceinline__ float sigmf(float x){ return 1.f/(1.f+__expf(-x)); }
__device__ __forceinline__ u64 fma2(u64 a, u64 b, u64 c){
    u64 d; asm("fma.rn.f32x2 %0, %1, %2, %3;" : "=l"(d) : "l"(a), "l"(b), "l"(c));
    return d;
}
__device__ __forceinline__ float2 unpack2(u64 a){
    float2 r; asm("mov.b64 {%0,%1}, %2;" : "=f"(r.x), "=f"(r.y) : "l"(a));
    return r;
}
__device__ __forceinline__ u64 swap64(u64 a){
    u64 d;
    asm("{\n\t.reg .b32 lo, hi;\n\tmov.b64 {lo,hi}, %1;\n\tmov.b64 %0, {hi,lo};\n\t}"
        : "=l"(d) : "l"(a));
    return d;
}

// ---------------------------------------------------------------------------
// One-launch precompute. Blocks [0, NLAYERS*(TROWS+1)) build the wi(r) table
// and the constant intra-edge weights; the LAST block runs the serial node-1
// scalar trajectory (with an L2 prefetch of Ws to de-serialize cold DRAM).
// ---------------------------------------------------------------------------
__global__ void e3nn_precompute(const float* __restrict__ Wr1,
                                const float* __restrict__ br1,
                                const float* __restrict__ Wr2,
                                const float* __restrict__ W_embed,
                                const float* __restrict__ Ws)
{
    const int tid = threadIdx.x;
    if (blockIdx.x == NLAYERS*(TROWS+1)) {
        // ---- serial s1 chain ----
        __shared__ float s1[CC];
        float pf = 0.f;
        for (int i = tid; i < NLAYERS*CC*CC; i += 128) pf += Ws[i];   // L2 warm
        if (pf == 1.2345e30f) g_dummy = pf;
        if (tid < CC) s1[tid] = W_embed[tid] + W_embed[CC + tid];
        __syncthreads();
        for (int l = 0; l < NLAYERS; l++) {
            float acc = 0.f;
            if (tid < CC) {
                g_s1[l][tid] = s1[tid];
                #pragma unroll 5
                for (int c = 0; c < CC; c++) acc += s1[c]*Ws[(l*CC + c)*CC + tid];
            }
            __syncthreads();
            if (tid < CC) s1[tid] = siluf(acc);
            __syncthreads();
        }
        return;
    }
    const int l   = blockIdx.x / (TROWS+1);
    const int row = blockIdx.x - l*(TROWS+1);
    const bool intra = (row == TROWS);
    float r;
    if (intra) r = HALFBAR;
    else {
        int knot = row - 1;
        knot = knot < 0 ? 0 : (knot > TKNOTS ? TKNOTS : knot);
        r = (float)knot * (MAXR/(float)TKNOTS);
    }
    __shared__ float emb[NB+2], hid[HID], fcs;
    if (tid == 0) {
        float tt = fminf(fmaxf(r/MAXR, 0.f), 1.f);
        float fc = 0.5f*(cosf(PI_F*tt) + 1.f);
        fcs = fc;
        const float width = MAXR/(float)(NB-1);
        for (int i = 0; i < NB; i++) {
            float ci = MAXR*(float)i/(float)(NB-1);
            float d  = (r - ci)/width;
            emb[i]   = __expf(-d*d)*fc;
        }
        emb[NB]   = intra ? 0.f : 1.f;
        emb[NB+1] = intra ? 1.f : 0.f;
    }
    __syncthreads();
    if (tid < HID) {
        float acc = br1[l*HID + tid];
        #pragma unroll
        for (int i = 0; i < NB+2; i++) acc += emb[i]*Wr1[(l*(NB+2)+i)*HID + tid];
        hid[tid] = siluf(acc);
    }
    __syncthreads();
    if (intra) {
        for (int ch = tid; ch < NPATHS*CC; ch += 128) {
            float acc = 0.f;
            for (int j = 0; j < HID; j++)
                acc += hid[j]*Wr2[(l*HID + j)*(NPATHS*CC) + ch];
            g_wbar[l][ch] = acc*fcs;
        }
    } else if (tid < 100) {
        int k = tid >> 2, sub = tid & 3;
        int ch = (sub < 2) ? (2*k + sub) : (50 + 2*k + (sub-2));
        float acc = 0.f;
        for (int j = 0; j < HID; j++)
            acc += hid[j]*Wr2[(l*HID + j)*(NPATHS*CC) + ch];
        g_witab[l][row][tid] = acc*fcs;
    }
}

// ---------------------------------------------------------------------------
// Main fused kernel: t-pair-packed hb + f32x2 GEMM.
// ---------------------------------------------------------------------------
__global__ void __launch_bounds__(NTHREADS, 3) e3nn_main(
    const float* __restrict__ y,
    const float* __restrict__ W_embed,
    const float* __restrict__ Ws,
    const float* __restrict__ Wv,
    const float* __restrict__ Wg,
    const float* __restrict__ W_out,
    float* __restrict__ outp)
{
    extern __shared__ float sm[];
    const int tid  = threadIdx.x;
    const int w    = tid >> 5;
    const int lane = tid & 31;
    const int k    = lane;
    const bool act = (k < 25);
    const int c0   = 2*k;
    const int c1   = c0 + 1;

    const int gbase = blockIdx.x*TPB + w*TRIPW;
    float* hbW = sm + OFF_HVT + w*HB_WARP;

    // zero whole hb region once (pads at c-index 50,51 stay 0 forever)
    for (int i = tid; i < WPB*HB_WARP; i += NTHREADS) sm[OFF_HVT + i] = 0.f;

    // ---- geometry init ----
    float myUIx=0.f, myUIy=0.f, myU3x=0.f, myU3y=0.f, myR=1e9f;
    if (lane < TRIPW) {
        int g = gbase + lane;
        int b = g >> 9;
        int t = g & 511;
        const float* yb = y + ((size_t)b*LL + t)*6;
        float p0x = yb[0],  p0y = yb[1];
        float p1x = yb[6],  p1y = yb[7];
        float a   = yb[8];
        float ex = p0x - p1x, ey = p0y - p1y;
        float r  = sqrtf(ex*ex + ey*ey);
        float inv = 1.f/(r + 1e-12f);
        myUIx = ex*inv; myUIy = ey*inv;
        myU3x = sinf(a); myU3y = -cosf(a);
        myR = r;
    }
    float uIx[TRIPW], uIy[TRIPW], u3x[TRIPW], u3y[TRIPW], rT[TRIPW];
    #pragma unroll
    for (int t = 0; t < TRIPW; t++) {
        uIx[t] = __shfl_sync(0xffffffffu, myUIx, t);
        uIy[t] = __shfl_sync(0xffffffffu, myUIy, t);
        u3x[t] = __shfl_sync(0xffffffffu, myU3x, t);
        u3y[t] = __shfl_sync(0xffffffffu, myU3y, t);
        rT[t]  = __shfl_sync(0xffffffffu, myR,  t);
    }

    // ---- register state ----
    float s[TRIPW][3][2];
    float v[TRIPW][3][2][3];
    #pragma unroll
    for (int t = 0; t < TRIPW; t++)
        #pragma unroll
        for (int n = 0; n < 3; n++)
            #pragma unroll
            for (int q = 0; q < 2; q++) {
                s[t][n][q] = 0.f;
                v[t][n][q][0] = v[t][n][q][1] = v[t][n][q][2] = 0.f;
            }
    if (act) {
        float e00 = W_embed[c0],      e01 = W_embed[c1];
        float e10 = W_embed[CC+c0],   e11 = W_embed[CC+c1];
        float e20 = W_embed[2*CC+c0], e21 = W_embed[2*CC+c1];
        #pragma unroll
        for (int t = 0; t < TRIPW; t++) {
            s[t][0][0] = e00 + e20;  s[t][0][1] = e01 + e21;
            s[t][1][0] = e00 + e10;  s[t][1][1] = e01 + e11;
            s[t][2][0] = e00 + e20;  s[t][2][1] = e01 + e21;
        }
    }

    for (int l = 0; l < NLAYERS; l++) {
        __syncthreads();   // prior GEMM done reading weight buf (l=0: hb zeroed)
        // ---- stage Ws/Wg/Wv (contiguous float4) + zero pad rows 50,51 ----
        {
            const float4* sa = (const float4*)(Ws + (size_t)l*CC*CC);
            const float4* sb = (const float4*)(Wg + (size_t)l*CC*CC);
            const float4* sc = (const float4*)(Wv + (size_t)l*CC*CC);
            float4* da = (float4*)(sm + WSS_OFF);
            float4* db = (float4*)(sm + WGS_OFF);
            float4* dc = (float4*)(sm + WVS_OFF);
            for (int i = tid; i < 625; i += NTHREADS) { da[i]=sa[i]; db[i]=sb[i]; dc[i]=sc[i]; }
            for (int i = tid; i < 100; i += NTHREADS) {
                sm[WSS_OFF + 2500 + i] = 0.f;
                sm[WGS_OFF + 2500 + i] = 0.f;
                sm[WVS_OFF + 2500 + i] = 0.f;
            }
        }
        // ---- inter-edge weights via Catmull-Rom table ----
        float wi[TRIPW][4];
        if (act) {
            #pragma unroll
            for (int t = 0; t < TRIPW; t++) {
                float xr = rT[t]*((float)TKNOTS/MAXR);
                float valid = (xr < (float)TKNOTS) ? 1.f : 0.f;
                xr = fminf(xr, (float)TKNOTS - 0.001f);
                float jf = floorf(xr);
                int j = (int)jf;
                float u = xr - jf;
                float u2 = u*u, u3 = u2*u;
                float cw0 = 0.5f*(-u + 2.f*u2 - u3);
                float cw1 = 0.5f*(2.f - 5.f*u2 + 3.f*u3);
                float cw2 = 0.5f*(u + 4.f*u2 - 3.f*u3);
                float cw3 = 0.5f*(-u2 + u3);
                const float* tb = &g_witab[l][j][4*k];
                float4 r0 = *(const float4*)(tb);
                float4 r1 = *(const float4*)(tb + 100);
                float4 r2 = *(const float4*)(tb + 200);
                float4 r3 = *(const float4*)(tb + 300);
                wi[t][0] = valid*(cw0*r0.x + cw1*r1.x + cw2*r2.x + cw3*r3.x);
                wi[t][1] = valid*(cw0*r0.y + cw1*r1.y + cw2*r2.y + cw3*r3.y);
                wi[t][2] = valid*(cw0*r0.z + cw1*r1.z + cw2*r2.z + cw3*r3.z);
                wi[t][3] = valid*(cw0*r0.w + cw1*r1.w + cw2*r2.w + cw3*r3.w);
            }
        }
        // ---- messages -> hb, t-pair packed: hb[tp][row][c*2 + j] ----
        if (act) {
            float wb0[2], wb1[2], wb2[2], wb3[2], wb4[2], s1v[2];
            #pragma unroll
            for (int q = 0; q < 2; q++) {
                int cq = c0 + q;
                wb0[q] = g_wbar[l][cq];
                wb1[q] = g_wbar[l][50+cq];
                wb2[q] = g_wbar[l][100+cq];
                wb3[q] = g_wbar[l][150+cq];
                wb4[q] = g_wbar[l][200+cq];
                s1v[q] = g_s1[l][cq];
            }
            #pragma unroll
            for (int tp = 0; tp < 2; tp++) {
                float* hb = hbW + tp*HB_TP;
                #pragma unroll
                for (int q = 0; q < 2; q++) {
                    float H3[2], H4[2], H5[2];
                    float V3[2][3], V4[2][3], V5[2][3];
                    #pragma unroll
                    for (int j = 0; j < 2; j++) {
                        const int t = 2*tp + j;
                        float ux = u3x[t], uy = u3y[t];
                        float s4  = s[t][1][q];
                        float v4x = v[t][1][q][0], v4y = v[t][1][q][1], v4z = v[t][1][q][2];
                        H4[j] = s4 + wi[t][q]*s1v[q];
                        float w1i = wi[t][2+q]*s1v[q];
                        V4[j][0] = v4x + w1i*uIx[t];
                        V4[j][1] = v4y + w1i*uIy[t];
                        V4[j][2] = v4z;
                        float dotc = v4x*ux + v4y*uy;
                        float base = wb0[q]*s4;
                        H3[j] = s[t][0][q] + base + wb2[q]*dotc;
                        H5[j] = s[t][2][q] + base - wb2[q]*dotc;
                        float cx = -v4z*uy, cy = v4z*ux, cz = v4x*uy - v4y*ux;
                        float y2x = dotc*ux - v4x*(1.f/3.f);
                        float y2y = dotc*uy - v4y*(1.f/3.f);
                        float y2z = -v4z*(1.f/3.f);
                        float sx = wb1[q]*s4;
                        V3[j][0] = v[t][0][q][0] + sx*ux + wb3[q]*cx + wb4[q]*y2x;
                        V3[j][1] = v[t][0][q][1] + sx*uy + wb3[q]*cy + wb4[q]*y2y;
                        V3[j][2] = v[t][0][q][2]         + wb3[q]*cz + wb4[q]*y2z;
                        V5[j][0] = v[t][2][q][0] - sx*ux - wb3[q]*cx + wb4[q]*y2x;
                        V5[j][1] = v[t][2][q][1] - sx*uy - wb3[q]*cy + wb4[q]*y2y;
                        V5[j][2] = v[t][2][q][2]         - wb3[q]*cz + wb4[q]*y2z;
                    }
                    const int ce = (c0 + q)*2;
                    *(float2*)&hb[0*HB_ROW + ce] = make_float2(H3[0], H3[1]);
                    *(float2*)&hb[1*HB_ROW + ce] = make_float2(H4[0], H4[1]);
                    *(float2*)&hb[2*HB_ROW + ce] = make_float2(H5[0], H5[1]);
                    #pragma unroll
                    for (int d = 0; d < 3; d++) {
                        *(float2*)&hb[(3 + 0*3 + d)*HB_ROW + ce] = make_float2(V3[0][d], V3[1][d]);
                        *(float2*)&hb[(3 + 1*3 + d)*HB_ROW + ce] = make_float2(V4[0][d], V4[1][d]);
                        *(float2*)&hb[(3 + 2*3 + d)*HB_ROW + ce] = make_float2(V5[0][d], V5[1][d]);
                    }
                }
            }
        }
        __syncthreads();   // weights staged + hb written
        // ---- node update GEMM with f32x2 diag/cross accumulators ----
        if (act) {
            #pragma unroll 1
            for (int n = 0; n < 3; n++) {
                u64 DS[2], XS[2], DG[2], XG[2];
                u64 DVx[2], XVx[2], DVy[2], XVy[2], DVz[2], XVz[2];
                #pragma unroll
                for (int tp = 0; tp < 2; tp++) {
                    DS[tp]=XS[tp]=DG[tp]=XG[tp]=0ull;
                    DVx[tp]=XVx[tp]=DVy[tp]=XVy[tp]=DVz[tp]=XVz[tp]=0ull;
                }
                #pragma unroll 1
                for (int cg = 0; cg < 52; cg += 4) {
                    u64 wsp[4], wgp[4], wvp[4], wss[4], wgs[4], wvs[4];
                    #pragma unroll
                    for (int i = 0; i < 4; i++) {
                        wsp[i] = *(const u64*)&sm[WSS_OFF + (cg+i)*CC + c0];
                        wgp[i] = *(const u64*)&sm[WGS_OFF + (cg+i)*CC + c0];
                        wvp[i] = *(const u64*)&sm[WVS_OFF + (cg+i)*CC + c0];
                        wss[i] = swap64(wsp[i]);
                        wgs[i] = swap64(wgp[i]);
                        wvs[i] = swap64(wvp[i]);
                    }
                    #pragma unroll
                    for (int tp = 0; tp < 2; tp++) {
                        const float* hb = hbW + tp*HB_TP;
                        ulonglong2 hA  = *(const ulonglong2*)&hb[n*HB_ROW + cg*2];
                        ulonglong2 hB  = *(const ulonglong2*)&hb[n*HB_ROW + cg*2 + 4];
                        ulonglong2 xA  = *(const ulonglong2*)&hb[(3+n*3+0)*HB_ROW + cg*2];
                        ulonglong2 xB  = *(const ulonglong2*)&hb[(3+n*3+0)*HB_ROW + cg*2 + 4];
                        ulonglong2 yA  = *(const ulonglong2*)&hb[(3+n*3+1)*HB_ROW + cg*2];
                        ulonglong2 yB  = *(const ulonglong2*)&hb[(3+n*3+1)*HB_ROW + cg*2 + 4];
                        ulonglong2 zA  = *(const ulonglong2*)&hb[(3+n*3+2)*HB_ROW + cg*2];
                        ulonglong2 zB  = *(const ulonglong2*)&hb[(3+n*3+2)*HB_ROW + cg*2 + 4];
                        u64 hu[4] = {hA.x, hA.y, hB.x, hB.y};
                        u64 xu[4] = {xA.x, xA.y, xB.x, xB.y};
                        u64 yu[4] = {yA.x, yA.y, yB.x, yB.y};
                        u64 zu[4] = {zA.x, zA.y, zB.x, zB.y};
                        #pragma unroll
                        for (int i = 0; i < 4; i++) {
                            DS[tp]  = fma2(hu[i], wsp[i], DS[tp]);
                            XS[tp]  = fma2(hu[i], wss[i], XS[tp]);
                            DG[tp]  = fma2(hu[i], wgp[i], DG[tp]);
                            XG[tp]  = fma2(hu[i], wgs[i], XG[tp]);
                            DVx[tp] = fma2(xu[i], wvp[i], DVx[tp]);
                            XVx[tp] = fma2(xu[i], wvs[i], XVx[tp]);
                            DVy[tp] = fma2(yu[i], wvp[i], DVy[tp]);
                            XVy[tp] = fma2(yu[i], wvs[i], XVy[tp]);
                            DVz[tp] = fma2(zu[i], wvp[i], DVz[tp]);
                            XVz[tp] = fma2(zu[i], wvs[i], XVz[tp]);
                        }
                    }
                }
                // unscramble: D=(t0*o0, t1*o1), X=(t0*o1, t1*o0)
                #pragma unroll
                for (int tp = 0; tp < 2; tp++) {
                    const int t0 = 2*tp, t1 = 2*tp + 1;
                    float2 ds = unpack2(DS[tp]),  xs = unpack2(XS[tp]);
                    float2 dg = unpack2(DG[tp]),  xg = unpack2(XG[tp]);
                    float2 dx = unpack2(DVx[tp]), cx = unpack2(XVx[tp]);
                    float2 dy = unpack2(DVy[tp]), cy = unpack2(XVy[tp]);
                    float2 dz = unpack2(DVz[tp]), cz = unpack2(XVz[tp]);
                    float g00 = sigmf(dg.x), g01 = sigmf(xg.x);
                    float g11 = sigmf(dg.y), g10 = sigmf(xg.y);
                    s[t0][n][0] = siluf(ds.x);  s[t0][n][1] = siluf(xs.x);
                    s[t1][n][1] = siluf(ds.y);  s[t1][n][0] = siluf(xs.y);
                    v[t0][n][0][0] = dx.x*g00;  v[t0][n][1][0] = cx.x*g01;
                    v[t1][n][1][0] = dx.y*g11;  v[t1][n][0][0] = cx.y*g10;
                    v[t0][n][0][1] = dy.x*g00;  v[t0][n][1][1] = cy.x*g01;
                    v[t1][n][1][1] = dy.y*g11;  v[t1][n][0][1] = cy.y*g10;
                    v[t0][n][0][2] = dz.x*g00;  v[t0][n][1][2] = cz.x*g01;
                    v[t1][n][1][2] = dz.y*g11;  v[t1][n][0][2] = cz.y*g10;
                }
            }
        }
    }

    // ---- epilogue ----
    float p[TRIPW][9];
    #pragma unroll
    for (int t = 0; t < TRIPW; t++)
        #pragma unroll
        for (int i = 0; i < 9; i++) p[t][i] = 0.f;
    if (act) {
        #pragma unroll
        for (int q = 0; q < 2; q++) {
            float wo = W_out[c0+q];
            #pragma unroll
            for (int t = 0; t < TRIPW; t++)
                #pragma unroll
                for (int n = 0; n < 3; n++)
                    #pragma unroll
                    for (int d = 0; d < 3; d++)
                        p[t][n*3+d] += wo*v[t][n][q][d];
        }
    }
    #pragma unroll
    for (int off = 16; off > 0; off >>= 1)
        #pragma unroll
        for (int t = 0; t < TRIPW; t++)
            #pragma unroll
            for (int i = 0; i < 9; i++)
                p[t][i] += __shfl_xor_sync(0xffffffffu, p[t][i], off);
    if (lane == 0) {
        #pragma unroll
        for (int t = 0; t < TRIPW; t++) {
            int g = gbase + t;
            int b = g >> 9;
            int tt = g & 511;
            float rx = p[t][0] + p[t][3] + p[t][6];
            float ry = p[t][1] + p[t][4] + p[t][7];
            float offx = -HALFBAR*u3x[t], offy = -HALFBAR*u3y[t];
            float rz = (offx*p[t][1] - offy*p[t][0]) - (offx*p[t][7] - offy*p[t][6]);
            float* o = outp + ((size_t)b*LL + (tt+1))*3;
            o[0] = rx; o[1] = ry; o[2] = rz;
        }
    }
}

// ---------------------------------------------------------------------------
extern "C" void kernel_launch(void* const* d_in, const int* in_sizes, int n_in,
                              void* d_out, int out_size)
{
    const float* y       = (const float*)d_in[0];
    const float* W_embed = (const float*)d_in[1];
    const float* Wr1     = (const float*)d_in[2];
    const float* br1     = (const float*)d_in[3];
    const float* Wr2     = (const float*)d_in[4];
    const float* Ws      = (const float*)d_in[5];
    const float* Wv      = (const float*)d_in[6];
    const float* Wg      = (const float*)d_in[7];
    const float* W_out   = (const float*)d_in[8];
    float* outp = (float*)d_out;

    cudaFuncSetAttribute(e3nn_main, cudaFuncAttributeMaxDynamicSharedMemorySize, SMEM_BYTES);

    cudaMemsetAsync(d_out, 0, (size_t)out_size*sizeof(float), 0);
    e3nn_precompute<<<NLAYERS*(TROWS+1) + 1, 128>>>(Wr1, br1, Wr2, W_embed, Ws);
    e3nn_main<<<NBLOCKS, NTHREADS, SMEM_BYTES>>>(y, W_embed, Ws, Wv, Wg, W_out, outp);
}